// round 5
// baseline (speedup 1.0000x reference)
#include <cuda_runtime.h>

namespace {
constexpr int B_ = 8, N_ = 1024, DIM = 512, H_ = 8, DH = 64, INNER = 512, G = 64;
constexpr float SCALE = 0.125f;
}

// Scratch (device globals — allocation-free rule)
__device__ float g_q[(size_t)G * N_ * DH];
__device__ float g_k[(size_t)G * N_ * DH];
__device__ float g_v[(size_t)G * N_ * DH];
__device__ float g_y[(size_t)B_ * N_ * INNER];
__device__ float g_ml[G * N_];
__device__ float g_isl[G * N_];
__device__ float g_w2[DIM * INNER];
__device__ float g_b2[DIM];

// ---------------------------------------------------------------------------
// tf32 helpers
// ---------------------------------------------------------------------------
__device__ __forceinline__ float cvt_tf32f(float x) {
    unsigned r;
    asm("cvt.rna.tf32.f32 %0, %1;" : "=r"(r) : "f"(x));
    return __uint_as_float(r);
}

__device__ __forceinline__ void mma8(float* d, const unsigned* a, const unsigned* b) {
    asm("mma.sync.aligned.m16n8k8.row.col.f32.tf32.tf32.f32 "
        "{%0,%1,%2,%3}, {%4,%5,%6,%7}, {%8,%9}, {%0,%1,%2,%3};"
        : "+f"(d[0]), "+f"(d[1]), "+f"(d[2]), "+f"(d[3])
        : "r"(a[0]), "r"(a[1]), "r"(a[2]), "r"(a[3]), "r"(b[0]), "r"(b[1]));
}

// One BK=32 slab of mma over smem tiles.
template <int MT, int NT, int WARPS_N, bool BKMAJ, int ASTR, int BSTR>
__device__ __forceinline__ void mma_slab(const float* As, const float* Bs,
                                         int warp, int g8, int t4,
                                         float (&acc)[MT][NT][4]) {
    const int wm = warp / WARPS_N, wn = warp % WARPS_N;
#pragma unroll
    for (int ks = 0; ks < 4; ks++) {
        const int c = ks * 8 + t4;
        unsigned af[MT][4], bf[NT][2];
#pragma unroll
        for (int mt = 0; mt < MT; mt++) {
            int r = wm * (MT * 16) + mt * 16 + g8;
            af[mt][0] = __float_as_uint(As[r * ASTR + c]);
            af[mt][1] = __float_as_uint(As[(r + 8) * ASTR + c]);
            af[mt][2] = __float_as_uint(As[r * ASTR + c + 4]);
            af[mt][3] = __float_as_uint(As[(r + 8) * ASTR + c + 4]);
        }
#pragma unroll
        for (int nt = 0; nt < NT; nt++) {
            int n = wn * (NT * 8) + nt * 8 + g8;
            if constexpr (BKMAJ) {
                bf[nt][0] = __float_as_uint(Bs[c * BSTR + n]);
                bf[nt][1] = __float_as_uint(Bs[(c + 4) * BSTR + n]);
            } else {
                bf[nt][0] = __float_as_uint(Bs[n * BSTR + c]);
                bf[nt][1] = __float_as_uint(Bs[n * BSTR + c + 4]);
            }
        }
#pragma unroll
        for (int mt = 0; mt < MT; mt++)
#pragma unroll
            for (int nt = 0; nt < NT; nt++)
                mma8(acc[mt][nt], af[mt], bf[nt]);
    }
}

// Register-staged 128x32 tile: LDG into regs, STS (with tf32 cvt + scale).
struct R4T { float4 a[4]; };
__device__ __forceinline__ void ldg4(R4T& r, const float* g, int ld) {
    const int t = threadIdx.x;
    const int rr = t >> 3, c4 = (t & 7) * 4;
#pragma unroll
    for (int p = 0; p < 4; p++)
        r.a[p] = *(const float4*)(g + (size_t)(rr + p * 32) * ld + c4);
}
template <int STR>
__device__ __forceinline__ void sts4(float* S, const R4T& r, float scale) {
    const int t = threadIdx.x;
    const int rr = t >> 3, c4 = (t & 7) * 4;
#pragma unroll
    for (int p = 0; p < 4; p++) {
        float4 v = r.a[p];
        float4 o;
        o.x = cvt_tf32f(v.x * scale);
        o.y = cvt_tf32f(v.y * scale);
        o.z = cvt_tf32f(v.z * scale);
        o.w = cvt_tf32f(v.w * scale);
        *(float4*)(S + (rr + p * 32) * STR + c4) = o;
    }
}

// ---------------------------------------------------------------------------
// K1: qkv = x @ w_qkv^T  -> head-major q/k/v  (double-buffered, 1 sync/slab)
// ---------------------------------------------------------------------------
__global__ __launch_bounds__(256) void k_qkv(const float* __restrict__ x,
                                             const float* __restrict__ w) {
    __shared__ float As[2][128 * 36], Bs[2][128 * 36];
    const int t = threadIdx.x, warp = t >> 5, lane = t & 31;
    const int g8 = lane >> 2, t4 = lane & 3;
    const int n0 = blockIdx.x * 128, m0 = blockIdx.y * 128;
    float acc[4][4][4] = {};
    R4T ra, rb;
    ldg4(ra, x + (size_t)m0 * DIM, DIM);
    ldg4(rb, w + (size_t)n0 * DIM, DIM);
    sts4<36>(As[0], ra, 1.f);
    sts4<36>(Bs[0], rb, 1.f);
    __syncthreads();
    int cur = 0;
    for (int k0 = 32; k0 < DIM; k0 += 32) {
        ldg4(ra, x + (size_t)m0 * DIM + k0, DIM);
        ldg4(rb, w + (size_t)n0 * DIM + k0, DIM);
        mma_slab<4, 4, 4, false, 36, 36>(As[cur], Bs[cur], warp, g8, t4, acc);
        sts4<36>(As[cur ^ 1], ra, 1.f);
        sts4<36>(Bs[cur ^ 1], rb, 1.f);
        __syncthreads();
        cur ^= 1;
    }
    mma_slab<4, 4, 4, false, 36, 36>(As[cur], Bs[cur], warp, g8, t4, acc);
    const int wm = warp >> 2, wn = warp & 3;
#pragma unroll
    for (int mt = 0; mt < 4; mt++)
#pragma unroll
        for (int nt = 0; nt < 4; nt++) {
            int col = n0 + wn * 32 + nt * 8 + 2 * t4;
            int part = col >> 9, h = (col >> 6) & 7, d = col & 63;
            float* dst = part == 0 ? g_q : (part == 1 ? g_k : g_v);
#pragma unroll
            for (int half = 0; half < 2; half++) {
                int row = m0 + wm * 64 + mt * 16 + g8 + half * 8;
                int b = row >> 10, n = row & 1023;
                float2 val = half ? make_float2(acc[mt][nt][2], acc[mt][nt][3])
                                  : make_float2(acc[mt][nt][0], acc[mt][nt][1]);
                *(float2*)&dst[((size_t)((b * 8 + h) * 1024 + n)) * 64 + d] = val;
            }
        }
}

// ---------------------------------------------------------------------------
// K2: lidar softmax row stats. Resident A i-tile + double-buffered B ring.
// ---------------------------------------------------------------------------
__global__ __launch_bounds__(256) void k_lstats(const float* __restrict__ lidar) {
    __shared__ float Ali[128 * 72];
    __shared__ float Bs[2][128 * 36];
    __shared__ float red[4][128], bcast[128], mrun[128], srun[128];
    const int t = threadIdx.x, warp = t >> 5, lane = t & 31;
    const int g8 = lane >> 2, t4 = lane & 3;
    const int gidx = blockIdx.y, b = gidx >> 3, h = gidx & 7;
    const int i0 = blockIdx.x * 128;
    const float* base = lidar + (size_t)b * N_ * INNER + h * 64;
    const int wm = warp >> 2, wn = warp & 3;
    // resident A (both 32-K slabs, stride 72)
    {
        R4T r0, r1;
        ldg4(r0, base + (size_t)i0 * INNER, INNER);
        ldg4(r1, base + (size_t)i0 * INNER + 32, INNER);
        sts4<72>(Ali, r0, SCALE);
        sts4<72>(Ali + 32, r1, SCALE);
    }
    if (t < 128) { mrun[t] = -1e30f; srun[t] = 0.f; }
    R4T rb;
    ldg4(rb, base, INNER);           // jt=0, ks=0
    sts4<36>(Bs[0], rb, 1.f);
    __syncthreads();
    int cur = 0;
    float acc[4][4][4];
    for (int idx = 0; idx < 16; idx++) {
        const int ks = idx & 1;
        if (ks == 0) {
#pragma unroll
            for (int a = 0; a < 4; a++)
#pragma unroll
                for (int c = 0; c < 4; c++)
#pragma unroll
                    for (int e = 0; e < 4; e++) acc[a][c][e] = 0.f;
        }
        if (idx < 15) {
            int nxt = idx + 1;
            ldg4(rb, base + (size_t)((nxt >> 1) * 128) * INNER + (nxt & 1) * 32,
                 INNER);
        }
        mma_slab<4, 4, 4, false, 72, 36>(Ali + ks * 32, Bs[cur], warp, g8, t4, acc);
        if (idx < 15) sts4<36>(Bs[cur ^ 1], rb, 1.f);
        __syncthreads();
        cur ^= 1;
        if (ks == 1) {
            // reductions for this jt
            float vm[4][2];
#pragma unroll
            for (int mt = 0; mt < 4; mt++) {
                float a0 = -1e30f, a1 = -1e30f;
#pragma unroll
                for (int nt = 0; nt < 4; nt++) {
                    a0 = fmaxf(a0, fmaxf(acc[mt][nt][0], acc[mt][nt][1]));
                    a1 = fmaxf(a1, fmaxf(acc[mt][nt][2], acc[mt][nt][3]));
                }
#pragma unroll
                for (int off = 1; off <= 2; off <<= 1) {
                    a0 = fmaxf(a0, __shfl_xor_sync(~0u, a0, off));
                    a1 = fmaxf(a1, __shfl_xor_sync(~0u, a1, off));
                }
                vm[mt][0] = a0; vm[mt][1] = a1;
            }
            if (t4 == 0)
#pragma unroll
                for (int mt = 0; mt < 4; mt++) {
                    red[wn][wm * 64 + mt * 16 + g8] = vm[mt][0];
                    red[wn][wm * 64 + mt * 16 + g8 + 8] = vm[mt][1];
                }
            __syncthreads();
            if (t < 128) {
                float tm = fmaxf(fmaxf(red[0][t], red[1][t]),
                                 fmaxf(red[2][t], red[3][t]));
                bcast[t] = fmaxf(mrun[t], tm);
            }
            __syncthreads();
            float vs[4][2];
#pragma unroll
            for (int mt = 0; mt < 4; mt++) {
                int r = wm * 64 + mt * 16 + g8;
                float mn0 = bcast[r], mn1 = bcast[r + 8];
                float s0 = 0.f, s1 = 0.f;
#pragma unroll
                for (int nt = 0; nt < 4; nt++) {
                    s0 += __expf(acc[mt][nt][0] - mn0) + __expf(acc[mt][nt][1] - mn0);
                    s1 += __expf(acc[mt][nt][2] - mn1) + __expf(acc[mt][nt][3] - mn1);
                }
#pragma unroll
                for (int off = 1; off <= 2; off <<= 1) {
                    s0 += __shfl_xor_sync(~0u, s0, off);
                    s1 += __shfl_xor_sync(~0u, s1, off);
                }
                vs[mt][0] = s0; vs[mt][1] = s1;
            }
            __syncthreads();
            if (t4 == 0)
#pragma unroll
                for (int mt = 0; mt < 4; mt++) {
                    red[wn][wm * 64 + mt * 16 + g8] = vs[mt][0];
                    red[wn][wm * 64 + mt * 16 + g8 + 8] = vs[mt][1];
                }
            __syncthreads();
            if (t < 128) {
                float ts = red[0][t] + red[1][t] + red[2][t] + red[3][t];
                float mn = bcast[t];
                srun[t] = srun[t] * __expf(mrun[t] - mn) + ts;
                mrun[t] = mn;
            }
            __syncthreads();
        }
    }
    if (t < 128) {
        g_ml[gidx * N_ + i0 + t] = mrun[t];
        g_isl[gidx * N_ + i0 + t] = 1.0f / srun[t];
    }
}

// ---------------------------------------------------------------------------
// K3 (flash): blend + online softmax + PV. LDGs issued one slab early.
// ---------------------------------------------------------------------------
__global__ __launch_bounds__(256, 1) void k_flash(const float* __restrict__ lidar,
                                                  const float* __restrict__ conv_w) {
    extern __shared__ float sm[];
    float* As = sm;                       // 128*36
    float* Bs = sm + 128 * 36;            // 128*36
    float* Ps = sm;                       // 128*132 (aliases As+Bs)
    float* Vs = sm + 128 * 132;           // 128*72
    float* mls = Vs + 128 * 72;
    float* isls = mls + 128;
    float* m_s = isls + 128;
    float* l_s = m_s + 128;
    float* al_s = l_s + 128;
    float* red = al_s + 128;              // 4*128

    const int t = threadIdx.x, warp = t >> 5, lane = t & 31;
    const int g8 = lane >> 2, t4 = lane & 3;
    const int gidx = blockIdx.y, i0 = blockIdx.x * 128;
    const int b = gidx >> 3, h = gidx & 7;
    const float c0 = conv_w[0], c1 = conv_w[1];
    const int wm = warp >> 2, wn = warp & 3;
    const int wm2 = warp >> 1, wn2 = warp & 1;

    if (t < 128) {
        mls[t] = g_ml[gidx * N_ + i0 + t];
        isls[t] = g_isl[gidx * N_ + i0 + t];
        m_s[t] = -1e30f;
        l_s[t] = 0.f;
    }
    const float* lbase = lidar + (size_t)b * N_ * INNER + h * 64;
    const float* qb = g_q + (size_t)gidx * N_ * DH;
    const float* kb = g_k + (size_t)gidx * N_ * DH;
    const float* vb = g_v + (size_t)gidx * N_ * DH;

    float acc_o[2][4][4] = {};

    for (int j0 = 0; j0 < N_; j0 += 128) {
        float acc[4][4][4] = {};
        R4T ra, rb;
        // slab0 (lidar k0=0)
        ldg4(ra, lbase + (size_t)i0 * INNER, INNER);
        ldg4(rb, lbase + (size_t)j0 * INNER, INNER);
        __syncthreads();                       // prev PV readers of Ps done
        sts4<36>(As, ra, SCALE); sts4<36>(Bs, rb, 1.f);
        ldg4(ra, lbase + (size_t)i0 * INNER + 32, INNER);   // slab1 ldg
        ldg4(rb, lbase + (size_t)j0 * INNER + 32, INNER);
        __syncthreads();
        mma_slab<4, 4, 4, false, 36, 36>(As, Bs, warp, g8, t4, acc);
        __syncthreads();
        sts4<36>(As, ra, SCALE); sts4<36>(Bs, rb, 1.f);
        ldg4(ra, qb + (size_t)i0 * DH, DH);                 // slab2 ldg
        ldg4(rb, kb + (size_t)j0 * DH, DH);
        __syncthreads();
        mma_slab<4, 4, 4, false, 36, 36>(As, Bs, warp, g8, t4, acc);
        // lidar softmax transform
#pragma unroll
        for (int mt = 0; mt < 4; mt++) {
            int r = wm * 64 + mt * 16 + g8;
            float m0v = mls[r], i0v = isls[r] * c1;
            float m1v = mls[r + 8], i1v = isls[r + 8] * c1;
#pragma unroll
            for (int nt = 0; nt < 4; nt++) {
                acc[mt][nt][0] = i0v * __expf(acc[mt][nt][0] - m0v);
                acc[mt][nt][1] = i0v * __expf(acc[mt][nt][1] - m0v);
                acc[mt][nt][2] = i1v * __expf(acc[mt][nt][2] - m1v);
                acc[mt][nt][3] = i1v * __expf(acc[mt][nt][3] - m1v);
            }
        }
        __syncthreads();
        sts4<36>(As, ra, c0 * SCALE); sts4<36>(Bs, rb, 1.f);
        ldg4(ra, qb + (size_t)i0 * DH + 32, DH);            // slab3 ldg
        ldg4(rb, kb + (size_t)j0 * DH + 32, DH);
        __syncthreads();
        mma_slab<4, 4, 4, false, 36, 36>(As, Bs, warp, g8, t4, acc);
        __syncthreads();
        sts4<36>(As, ra, c0 * SCALE); sts4<36>(Bs, rb, 1.f);
        __syncthreads();
        mma_slab<4, 4, 4, false, 36, 36>(As, Bs, warp, g8, t4, acc);
        // --- row max ---
        float vm[4][2];
#pragma unroll
        for (int mt = 0; mt < 4; mt++) {
            float a0 = -1e30f, a1 = -1e30f;
#pragma unroll
            for (int nt = 0; nt < 4; nt++) {
                a0 = fmaxf(a0, fmaxf(acc[mt][nt][0], acc[mt][nt][1]));
                a1 = fmaxf(a1, fmaxf(acc[mt][nt][2], acc[mt][nt][3]));
            }
#pragma unroll
            for (int off = 1; off <= 2; off <<= 1) {
                a0 = fmaxf(a0, __shfl_xor_sync(~0u, a0, off));
                a1 = fmaxf(a1, __shfl_xor_sync(~0u, a1, off));
            }
            vm[mt][0] = a0; vm[mt][1] = a1;
        }
        if (t4 == 0)
#pragma unroll
            for (int mt = 0; mt < 4; mt++) {
                red[wn * 128 + wm * 64 + mt * 16 + g8] = vm[mt][0];
                red[wn * 128 + wm * 64 + mt * 16 + g8 + 8] = vm[mt][1];
            }
        __syncthreads();
        if (t < 128) {
            float tm = fmaxf(fmaxf(red[t], red[128 + t]),
                             fmaxf(red[256 + t], red[384 + t]));
            float mo = m_s[t];
            float mn = fmaxf(mo, tm);
            al_s[t] = __expf(mo - mn);
            m_s[t] = mn;
        }
        __syncthreads();
        // --- p = exp(mid - m_new), write P (tf32) to smem, row sums ---
        float vs[4][2];
#pragma unroll
        for (int mt = 0; mt < 4; mt++) {
            int r = wm * 64 + mt * 16 + g8;
            float mn0 = m_s[r], mn1 = m_s[r + 8];
            float s0 = 0.f, s1 = 0.f;
#pragma unroll
            for (int nt = 0; nt < 4; nt++) {
                float p0 = __expf(acc[mt][nt][0] - mn0);
                float p1 = __expf(acc[mt][nt][1] - mn0);
                float p2 = __expf(acc[mt][nt][2] - mn1);
                float p3 = __expf(acc[mt][nt][3] - mn1);
                s0 += p0 + p1; s1 += p2 + p3;
                int cc = wn * 32 + nt * 8 + 2 * t4;
                *(float2*)&Ps[r * 132 + cc] =
                    make_float2(cvt_tf32f(p0), cvt_tf32f(p1));
                *(float2*)&Ps[(r + 8) * 132 + cc] =
                    make_float2(cvt_tf32f(p2), cvt_tf32f(p3));
            }
#pragma unroll
            for (int off = 1; off <= 2; off <<= 1) {
                s0 += __shfl_xor_sync(~0u, s0, off);
                s1 += __shfl_xor_sync(~0u, s1, off);
            }
            vs[mt][0] = s0; vs[mt][1] = s1;
        }
        if (t4 == 0)
#pragma unroll
            for (int mt = 0; mt < 4; mt++) {
                red[wn * 128 + wm * 64 + mt * 16 + g8] = vs[mt][0];
                red[wn * 128 + wm * 64 + mt * 16 + g8 + 8] = vs[mt][1];
            }
        // --- load V j-tile ---
        {
            int j = t >> 2, d16 = (t & 3) * 16;
#pragma unroll
            for (int p = 0; p < 2; p++) {
                int jj = j + p * 64;
                const float* src = vb + (size_t)(j0 + jj) * DH + d16;
#pragma unroll
                for (int q = 0; q < 4; q++) {
                    float4 v = *(const float4*)(src + q * 4);
                    float4 o;
                    o.x = cvt_tf32f(v.x); o.y = cvt_tf32f(v.y);
                    o.z = cvt_tf32f(v.z); o.w = cvt_tf32f(v.w);
                    *(float4*)(Vs + jj * 72 + d16 + q * 4) = o;
                }
            }
        }
        __syncthreads();
        if (t < 128)
            l_s[t] = l_s[t] * al_s[t] +
                     (red[t] + red[128 + t] + red[256 + t] + red[384 + t]);
#pragma unroll
        for (int mt = 0; mt < 2; mt++) {
            int r = wm2 * 32 + mt * 16 + g8;
            float a0 = al_s[r], a1 = al_s[r + 8];
#pragma unroll
            for (int nt = 0; nt < 4; nt++) {
                acc_o[mt][nt][0] *= a0; acc_o[mt][nt][1] *= a0;
                acc_o[mt][nt][2] *= a1; acc_o[mt][nt][3] *= a1;
            }
        }
        // --- O += P @ V ---
#pragma unroll
        for (int slab = 0; slab < 4; slab++)
            mma_slab<2, 4, 2, true, 132, 72>(Ps + slab * 32,
                                             Vs + (size_t)slab * 32 * 72,
                                             warp, g8, t4, acc_o);
    }
    __syncthreads();
    float* yb = g_y + (size_t)b * N_ * INNER + h * 64;
#pragma unroll
    for (int mt = 0; mt < 2; mt++) {
        int r = wm2 * 32 + mt * 16 + g8;
        float inv0 = 1.0f / l_s[r], inv1 = 1.0f / l_s[r + 8];
#pragma unroll
        for (int nt = 0; nt < 4; nt++) {
            int d = wn2 * 32 + nt * 8 + 2 * t4;
            int n = i0 + r;
            *(float2*)&yb[(size_t)n * INNER + d] =
                make_float2(acc_o[mt][nt][0] * inv0, acc_o[mt][nt][1] * inv0);
            *(float2*)&yb[(size_t)(n + 8) * INNER + d] =
                make_float2(acc_o[mt][nt][2] * inv1, acc_o[mt][nt][3] * inv1);
        }
    }
}

// ---------------------------------------------------------------------------
// K4: out = y @ W2^T + bias2  (double-buffered)
// ---------------------------------------------------------------------------
__global__ __launch_bounds__(256) void k_out(float* __restrict__ out) {
    __shared__ float As[2][128 * 36], Bs[2][128 * 36];
    const int t = threadIdx.x, warp = t >> 5, lane = t & 31;
    const int g8 = lane >> 2, t4 = lane & 3;
    const int n0 = blockIdx.x * 128, m0 = blockIdx.y * 128;
    float acc[4][4][4] = {};
    R4T ra, rb;
    ldg4(ra, g_y + (size_t)m0 * INNER, INNER);
    ldg4(rb, g_w2 + (size_t)n0 * INNER, INNER);
    sts4<36>(As[0], ra, 1.f);
    sts4<36>(Bs[0], rb, 1.f);
    __syncthreads();
    int cur = 0;
    for (int k0 = 32; k0 < INNER; k0 += 32) {
        ldg4(ra, g_y + (size_t)m0 * INNER + k0, INNER);
        ldg4(rb, g_w2 + (size_t)n0 * INNER + k0, INNER);
        mma_slab<4, 4, 4, false, 36, 36>(As[cur], Bs[cur], warp, g8, t4, acc);
        sts4<36>(As[cur ^ 1], ra, 1.f);
        sts4<36>(Bs[cur ^ 1], rb, 1.f);
        __syncthreads();
        cur ^= 1;
    }
    mma_slab<4, 4, 4, false, 36, 36>(As[cur], Bs[cur], warp, g8, t4, acc);
    const int wm = warp >> 2, wn = warp & 3;
#pragma unroll
    for (int mt = 0; mt < 4; mt++)
#pragma unroll
        for (int nt = 0; nt < 4; nt++) {
            int col = n0 + wn * 32 + nt * 8 + 2 * t4;
            float b0 = g_b2[col], b1 = g_b2[col + 1];
            int r = m0 + wm * 64 + mt * 16 + g8;
            *(float2*)&out[(size_t)r * DIM + col] =
                make_float2(acc[mt][nt][0] + b0, acc[mt][nt][1] + b1);
            *(float2*)&out[(size_t)(r + 8) * DIM + col] =
                make_float2(acc[mt][nt][2] + b0, acc[mt][nt][3] + b1);
        }
}

// ---------------------------------------------------------------------------
// Precompute: W2 = Wout(.,h-block) @ Wm ; bias2 = b_out + Wout b_merge~
// ---------------------------------------------------------------------------
__global__ __launch_bounds__(256) void k_w2(const float* __restrict__ w_merge,
                                            const float* __restrict__ w_out) {
    __shared__ float wm[64 * 64];
    const int t = threadIdx.x;
    for (int i = t; i < 4096; i += 256) wm[i] = w_merge[i];
    __syncthreads();
    int idx = blockIdx.x * 256 + t;
    int c = idx >> 9, i = idx & 511;
    int h = i >> 6, d = i & 63;
    const float* wo = w_out + (size_t)c * INNER + h * 64;
    float s = 0.f;
#pragma unroll 8
    for (int dp = 0; dp < 64; dp++) s += wo[dp] * wm[dp * 64 + d];
    g_w2[idx] = s;
}

__global__ __launch_bounds__(256) void k_bias2(const float* __restrict__ w_out,
                                               const float* __restrict__ b_merge,
                                               const float* __restrict__ b_out) {
    int c = blockIdx.x * 8 + (threadIdx.x >> 5);
    int lane = threadIdx.x & 31;
    float s = 0.f;
    for (int i = lane; i < INNER; i += 32)
        s += w_out[(size_t)c * INNER + i] * b_merge[i & 63];
    for (int o = 16; o; o >>= 1) s += __shfl_xor_sync(~0u, s, o);
    if (lane == 0) g_b2[c] = b_out[c] + s;
}

__global__ __launch_bounds__(256) void k_copy(const float* __restrict__ src,
                                              float* __restrict__ dst, int n4) {
    int i = blockIdx.x * blockDim.x + threadIdx.x;
    if (i < n4) ((float4*)dst)[i] = ((const float4*)src)[i];
}

extern "C" void kernel_launch(void* const* d_in, const int* in_sizes, int n_in,
                              void* d_out, int out_size) {
    const float* x       = (const float*)d_in[0];
    const float* lidar   = (const float*)d_in[1];
    const float* w_qkv   = (const float*)d_in[2];
    const float* w_merge = (const float*)d_in[3];
    const float* b_merge = (const float*)d_in[4];
    const float* w_out   = (const float*)d_in[5];
    const float* b_out   = (const float*)d_in[6];
    const float* conv_w  = (const float*)d_in[7];
    float* out = (float*)d_out;

    const int flashSmem = (128 * 132 + 128 * 72 + 9 * 128) * 4;
    cudaFuncSetAttribute(k_flash, cudaFuncAttributeMaxDynamicSharedMemorySize,
                         flashSmem);

    // launch order puts k_flash 4th (ncu captures launch #4)
    k_qkv<<<dim3(12, 64), 256>>>(x, w_qkv);
    k_lstats<<<dim3(8, G), 256>>>(lidar);
    k_w2<<<1024, 256>>>(w_merge, w_out);
    k_flash<<<dim3(8, G), 256, flashSmem>>>(lidar, conv_w);
    k_bias2<<<64, 256>>>(w_out, b_merge, b_out);
    k_out<<<dim3(4, 64), 256>>>(out);

    const int outElems = B_ * N_ * DIM;
    if (out_size >= 2 * outElems)
        k_copy<<<(outElems / 4 + 255) / 256, 256>>>(lidar, out + outElems,
                                                    outElems / 4);
}

// round 7
// speedup vs baseline: 1.0850x; 1.0850x over previous
#include <cuda_runtime.h>

namespace {
constexpr int B_ = 8, N_ = 1024, DIM = 512, H_ = 8, DH = 64, INNER = 512, G = 64;
constexpr float SCALE = 0.125f;
}

// Scratch (device globals — allocation-free rule)
__device__ float g_q[(size_t)G * N_ * DH];
__device__ float g_k[(size_t)G * N_ * DH];
__device__ float g_v[(size_t)G * N_ * DH];
__device__ float g_y[(size_t)B_ * N_ * INNER];
__device__ float g_ml[G * N_];
__device__ float g_isl[G * N_];
__device__ float g_w2[DIM * INNER];
__device__ float g_b2[DIM];

// ---------------------------------------------------------------------------
// tf32 helpers
// ---------------------------------------------------------------------------
__device__ __forceinline__ float cvt_tf32f(float x) {
    unsigned r;
    asm("cvt.rna.tf32.f32 %0, %1;" : "=r"(r) : "f"(x));
    return __uint_as_float(r);
}

__device__ __forceinline__ void mma8(float* d, const unsigned* a, const unsigned* b) {
    asm("mma.sync.aligned.m16n8k8.row.col.f32.tf32.tf32.f32 "
        "{%0,%1,%2,%3}, {%4,%5,%6,%7}, {%8,%9}, {%0,%1,%2,%3};"
        : "+f"(d[0]), "+f"(d[1]), "+f"(d[2]), "+f"(d[3])
        : "r"(a[0]), "r"(a[1]), "r"(a[2]), "r"(a[3]), "r"(b[0]), "r"(b[1]));
}

// Permuted layout: within each 8-col K group, logical col c sits at physical
// pos(c) = 2*(c&3) + ((c&4)>>2), XOR'd with ((row&3)<<1). A thread's fragment
// pair (c, c+4) with c = ks*8+t4 is then one contiguous float2.
template <int MT, int NT, int WARPS_N, int ASTR, int BSTR>
__device__ __forceinline__ void mma_slab_p(const float* As, const float* Bs,
                                           int warp, int g8, int t4,
                                           float (&acc)[MT][NT][4]) {
    const int wm = warp / WARPS_N, wn = warp % WARPS_N;
    const int sw = (g8 & 3) << 1;
    const int po = (2 * t4) ^ sw;
#pragma unroll
    for (int ks = 0; ks < 4; ks++) {
        const int off = ks * 8 + po;
        unsigned af[MT][4], bf[NT][2];
#pragma unroll
        for (int mt = 0; mt < MT; mt++) {
            int r = wm * (MT * 16) + mt * 16 + g8;
            float2 lo = *(const float2*)&As[r * ASTR + off];
            float2 hi = *(const float2*)&As[(r + 8) * ASTR + off];
            af[mt][0] = __float_as_uint(lo.x);
            af[mt][1] = __float_as_uint(hi.x);
            af[mt][2] = __float_as_uint(lo.y);
            af[mt][3] = __float_as_uint(hi.y);
        }
#pragma unroll
        for (int nt = 0; nt < NT; nt++) {
            int n = wn * (NT * 8) + nt * 8 + g8;
            float2 bv = *(const float2*)&Bs[n * BSTR + off];
            bf[nt][0] = __float_as_uint(bv.x);
            bf[nt][1] = __float_as_uint(bv.y);
        }
#pragma unroll
        for (int mt = 0; mt < MT; mt++)
#pragma unroll
            for (int nt = 0; nt < NT; nt++)
                mma8(acc[mt][nt], af[mt], bf[nt]);
    }
}

// PV: A = Ps (permuted, stride 136), B = Vs (k-major, unpermuted, stride 72).
__device__ __forceinline__ void mma_pv(const float* Ps_, const float* Vs_,
                                       int warp, int g8, int t4,
                                       float (&acc)[2][4][4]) {
    const int wm2 = warp >> 1, wn2 = warp & 1;
    const int sw = (g8 & 3) << 1;
    const int po = (2 * t4) ^ sw;
#pragma unroll
    for (int ks = 0; ks < 4; ks++) {
        const int off = ks * 8 + po;
        const int c = ks * 8 + t4;
        unsigned af[2][4], bf[4][2];
#pragma unroll
        for (int mt = 0; mt < 2; mt++) {
            int r = wm2 * 32 + mt * 16 + g8;
            float2 lo = *(const float2*)&Ps_[r * 136 + off];
            float2 hi = *(const float2*)&Ps_[(r + 8) * 136 + off];
            af[mt][0] = __float_as_uint(lo.x);
            af[mt][1] = __float_as_uint(hi.x);
            af[mt][2] = __float_as_uint(lo.y);
            af[mt][3] = __float_as_uint(hi.y);
        }
#pragma unroll
        for (int nt = 0; nt < 4; nt++) {
            int n = wn2 * 32 + nt * 8 + g8;
            bf[nt][0] = __float_as_uint(Vs_[c * 72 + n]);
            bf[nt][1] = __float_as_uint(Vs_[(c + 4) * 72 + n]);
        }
#pragma unroll
        for (int mt = 0; mt < 2; mt++)
#pragma unroll
            for (int nt = 0; nt < 4; nt++)
                mma8(acc[mt][nt], af[mt], bf[nt]);
    }
}

// Register-staged 128x32 tile: LDG into regs; permuted STS w/ tf32 cvt+scale.
struct R4T { float4 a[4]; };
__device__ __forceinline__ void ldg4(R4T& r, const float* g, int ld) {
    const int t = threadIdx.x;
    const int rr = t >> 3, c4 = (t & 7) * 4;
#pragma unroll
    for (int p = 0; p < 4; p++)
        r.a[p] = *(const float4*)(g + (size_t)(rr + p * 32) * ld + c4);
}
template <int STR>
__device__ __forceinline__ void sts4p(float* S, const R4T& r, float scale) {
    const int t = threadIdx.x;
    const int rr = t >> 3, c4 = (t & 7) * 4;
    const int start = (c4 & 24) + ((c4 & 4) ? 1 : 0);
    const int sw = (rr & 3) << 1;
#pragma unroll
    for (int p = 0; p < 4; p++) {
        float4 v = r.a[p];
        float* row = S + (rr + p * 32) * STR;
        row[(start + 0) ^ sw] = cvt_tf32f(v.x * scale);
        row[(start + 2) ^ sw] = cvt_tf32f(v.y * scale);
        row[(start + 4) ^ sw] = cvt_tf32f(v.z * scale);
        row[(start + 6) ^ sw] = cvt_tf32f(v.w * scale);
    }
}

// ---------------------------------------------------------------------------
// K1: qkv = x @ w_qkv^T  -> head-major q/k/v  (double-buffered)
// ---------------------------------------------------------------------------
__global__ __launch_bounds__(256) void k_qkv(const float* __restrict__ x,
                                             const float* __restrict__ w) {
    __shared__ float As[2][128 * 40], Bs[2][128 * 40];
    const int t = threadIdx.x, warp = t >> 5, lane = t & 31;
    const int g8 = lane >> 2, t4 = lane & 3;
    const int n0 = blockIdx.x * 128, m0 = blockIdx.y * 128;
    float acc[4][4][4] = {};
    R4T ra, rb;
    ldg4(ra, x + (size_t)m0 * DIM, DIM);
    ldg4(rb, w + (size_t)n0 * DIM, DIM);
    sts4p<40>(As[0], ra, 1.f);
    sts4p<40>(Bs[0], rb, 1.f);
    __syncthreads();
    int cur = 0;
    for (int k0 = 32; k0 < DIM; k0 += 32) {
        ldg4(ra, x + (size_t)m0 * DIM + k0, DIM);
        ldg4(rb, w + (size_t)n0 * DIM + k0, DIM);
        mma_slab_p<4, 4, 4, 40, 40>(As[cur], Bs[cur], warp, g8, t4, acc);
        sts4p<40>(As[cur ^ 1], ra, 1.f);
        sts4p<40>(Bs[cur ^ 1], rb, 1.f);
        __syncthreads();
        cur ^= 1;
    }
    mma_slab_p<4, 4, 4, 40, 40>(As[cur], Bs[cur], warp, g8, t4, acc);
    const int wm = warp >> 2, wn = warp & 3;
#pragma unroll
    for (int mt = 0; mt < 4; mt++)
#pragma unroll
        for (int nt = 0; nt < 4; nt++) {
            int col = n0 + wn * 32 + nt * 8 + 2 * t4;
            int part = col >> 9, h = (col >> 6) & 7, d = col & 63;
            float* dst = part == 0 ? g_q : (part == 1 ? g_k : g_v);
#pragma unroll
            for (int half = 0; half < 2; half++) {
                int row = m0 + wm * 64 + mt * 16 + g8 + half * 8;
                int b = row >> 10, n = row & 1023;
                float2 val = half ? make_float2(acc[mt][nt][2], acc[mt][nt][3])
                                  : make_float2(acc[mt][nt][0], acc[mt][nt][1]);
                *(float2*)&dst[((size_t)((b * 8 + h) * 1024 + n)) * 64 + d] = val;
            }
        }
}

// ---------------------------------------------------------------------------
// K2: lidar softmax row stats. Resident A + double-buffered B.
// ---------------------------------------------------------------------------
__global__ __launch_bounds__(256) void k_lstats(const float* __restrict__ lidar) {
    __shared__ float Ali[2][128 * 40];
    __shared__ float Bs[2][128 * 40];
    __shared__ float red[4][128], bcast[128], mrun[128], srun[128];
    const int t = threadIdx.x, warp = t >> 5, lane = t & 31;
    const int g8 = lane >> 2, t4 = lane & 3;
    const int gidx = blockIdx.y, b = gidx >> 3, h = gidx & 7;
    const int i0 = blockIdx.x * 128;
    const float* base = lidar + (size_t)b * N_ * INNER + h * 64;
    const int wm = warp >> 2, wn = warp & 3;
    {
        R4T r0;
        ldg4(r0, base + (size_t)i0 * INNER, INNER);
        sts4p<40>(Ali[0], r0, SCALE);
        ldg4(r0, base + (size_t)i0 * INNER + 32, INNER);
        sts4p<40>(Ali[1], r0, SCALE);
    }
    if (t < 128) { mrun[t] = -1e30f; srun[t] = 0.f; }
    R4T rb;
    ldg4(rb, base, INNER);
    sts4p<40>(Bs[0], rb, 1.f);
    __syncthreads();
    int cur = 0;
    float acc[4][4][4];
    for (int idx = 0; idx < 16; idx++) {
        const int ks = idx & 1;
        if (ks == 0) {
#pragma unroll
            for (int a = 0; a < 4; a++)
#pragma unroll
                for (int c = 0; c < 4; c++)
#pragma unroll
                    for (int e = 0; e < 4; e++) acc[a][c][e] = 0.f;
        }
        if (idx < 15) {
            int nxt = idx + 1;
            ldg4(rb, base + (size_t)((nxt >> 1) * 128) * INNER + (nxt & 1) * 32,
                 INNER);
        }
        mma_slab_p<4, 4, 4, 40, 40>(Ali[ks], Bs[cur], warp, g8, t4, acc);
        if (idx < 15) sts4p<40>(Bs[cur ^ 1], rb, 1.f);
        __syncthreads();
        cur ^= 1;
        if (ks == 1) {
            float vm[4][2];
#pragma unroll
            for (int mt = 0; mt < 4; mt++) {
                float a0 = -1e30f, a1 = -1e30f;
#pragma unroll
                for (int nt = 0; nt < 4; nt++) {
                    a0 = fmaxf(a0, fmaxf(acc[mt][nt][0], acc[mt][nt][1]));
                    a1 = fmaxf(a1, fmaxf(acc[mt][nt][2], acc[mt][nt][3]));
                }
#pragma unroll
                for (int off = 1; off <= 2; off <<= 1) {
                    a0 = fmaxf(a0, __shfl_xor_sync(~0u, a0, off));
                    a1 = fmaxf(a1, __shfl_xor_sync(~0u, a1, off));
                }
                vm[mt][0] = a0; vm[mt][1] = a1;
            }
            if (t4 == 0)
#pragma unroll
                for (int mt = 0; mt < 4; mt++) {
                    red[wn][wm * 64 + mt * 16 + g8] = vm[mt][0];
                    red[wn][wm * 64 + mt * 16 + g8 + 8] = vm[mt][1];
                }
            __syncthreads();
            if (t < 128) {
                float tm = fmaxf(fmaxf(red[0][t], red[1][t]),
                                 fmaxf(red[2][t], red[3][t]));
                bcast[t] = fmaxf(mrun[t], tm);
            }
            __syncthreads();
            float vs[4][2];
#pragma unroll
            for (int mt = 0; mt < 4; mt++) {
                int r = wm * 64 + mt * 16 + g8;
                float mn0 = bcast[r], mn1 = bcast[r + 8];
                float s0 = 0.f, s1 = 0.f;
#pragma unroll
                for (int nt = 0; nt < 4; nt++) {
                    s0 += __expf(acc[mt][nt][0] - mn0) + __expf(acc[mt][nt][1] - mn0);
                    s1 += __expf(acc[mt][nt][2] - mn1) + __expf(acc[mt][nt][3] - mn1);
                }
#pragma unroll
                for (int off = 1; off <= 2; off <<= 1) {
                    s0 += __shfl_xor_sync(~0u, s0, off);
                    s1 += __shfl_xor_sync(~0u, s1, off);
                }
                vs[mt][0] = s0; vs[mt][1] = s1;
            }
            __syncthreads();
            if (t4 == 0)
#pragma unroll
                for (int mt = 0; mt < 4; mt++) {
                    red[wn][wm * 64 + mt * 16 + g8] = vs[mt][0];
                    red[wn][wm * 64 + mt * 16 + g8 + 8] = vs[mt][1];
                }
            __syncthreads();
            if (t < 128) {
                float ts = red[0][t] + red[1][t] + red[2][t] + red[3][t];
                float mn = bcast[t];
                srun[t] = srun[t] * __expf(mrun[t] - mn) + ts;
                mrun[t] = mn;
            }
            __syncthreads();
        }
    }
    if (t < 128) {
        g_ml[gidx * N_ + i0 + t] = mrun[t];
        g_isl[gidx * N_ + i0 + t] = 1.0f / srun[t];
    }
}

// ---------------------------------------------------------------------------
// K3 (flash): resident i-tiles; blend + online softmax + PV.
// ---------------------------------------------------------------------------
__global__ __launch_bounds__(256, 1) void k_flash(const float* __restrict__ lidar,
                                                  const float* __restrict__ conv_w) {
    extern __shared__ float sm[];
    float* AliL0 = sm;
    float* AliL1 = sm + 5120;
    float* AliQ0 = sm + 10240;
    float* AliQ1 = sm + 15360;
    float* Bs    = sm + 20480;            // 128*40
    float* Vs    = sm + 25600;            // 128*72
    float* Ps    = sm + 34816;            // 128*136
    float* mls   = sm + 52224;
    float* isls  = mls + 128;
    float* m_s   = isls + 128;
    float* l_s   = m_s + 128;
    float* al_s  = l_s + 128;
    float* red   = al_s + 128;            // 4*128

    const int t = threadIdx.x, warp = t >> 5, lane = t & 31;
    const int g8 = lane >> 2, t4 = lane & 3;
    const int gidx = blockIdx.y, i0 = blockIdx.x * 128;
    const int b = gidx >> 3, h = gidx & 7;
    const float c0 = conv_w[0], c1 = conv_w[1];
    const int wm = warp >> 2, wn = warp & 3;
    const int wm2 = warp >> 1, wn2 = warp & 1;

    if (t < 128) {
        mls[t] = g_ml[gidx * N_ + i0 + t];
        isls[t] = g_isl[gidx * N_ + i0 + t];
        m_s[t] = -1e30f;
        l_s[t] = 0.f;
    }
    const float* lbase = lidar + (size_t)b * N_ * INNER + h * 64;
    const float* qb = g_q + (size_t)gidx * N_ * DH;
    const float* kb = g_k + (size_t)gidx * N_ * DH;
    const float* vb = g_v + (size_t)gidx * N_ * DH;

    // resident i-tiles (loaded once)
    R4T rb;
    ldg4(rb, lbase + (size_t)i0 * INNER, INNER);      sts4p<40>(AliL0, rb, SCALE);
    ldg4(rb, lbase + (size_t)i0 * INNER + 32, INNER); sts4p<40>(AliL1, rb, SCALE);
    ldg4(rb, qb + (size_t)i0 * DH, DH);               sts4p<40>(AliQ0, rb, c0 * SCALE);
    ldg4(rb, qb + (size_t)i0 * DH + 32, DH);          sts4p<40>(AliQ1, rb, c0 * SCALE);
    ldg4(rb, lbase, INNER);                            // first B slab (j0=0,k0)
    __syncthreads();

    float acc_o[2][4][4] = {};

    for (int j0 = 0; j0 < N_; j0 += 128) {
        float acc[4][4][4] = {};
        // slab 0 (lidar k0)
        sts4p<40>(Bs, rb, 1.f);
        ldg4(rb, lbase + (size_t)j0 * INNER + 32, INNER);
        __syncthreads();
        mma_slab_p<4, 4, 4, 40, 40>(AliL0, Bs, warp, g8, t4, acc);
        __syncthreads();
        // slab 1 (lidar k32)
        sts4p<40>(Bs, rb, 1.f);
        ldg4(rb, kb + (size_t)j0 * DH, DH);
        __syncthreads();
        mma_slab_p<4, 4, 4, 40, 40>(AliL1, Bs, warp, g8, t4, acc);
        // lidar softmax transform
#pragma unroll
        for (int mt = 0; mt < 4; mt++) {
            int r = wm * 64 + mt * 16 + g8;
            float m0v = mls[r], i0v = isls[r] * c1;
            float m1v = mls[r + 8], i1v = isls[r + 8] * c1;
#pragma unroll
            for (int nt = 0; nt < 4; nt++) {
                acc[mt][nt][0] = i0v * __expf(acc[mt][nt][0] - m0v);
                acc[mt][nt][1] = i0v * __expf(acc[mt][nt][1] - m0v);
                acc[mt][nt][2] = i1v * __expf(acc[mt][nt][2] - m1v);
                acc[mt][nt][3] = i1v * __expf(acc[mt][nt][3] - m1v);
            }
        }
        __syncthreads();
        // slab 2 (qk k0)
        sts4p<40>(Bs, rb, 1.f);
        ldg4(rb, kb + (size_t)j0 * DH + 32, DH);
        __syncthreads();
        mma_slab_p<4, 4, 4, 40, 40>(AliQ0, Bs, warp, g8, t4, acc);
        __syncthreads();
        // slab 3 (qk k32)
        sts4p<40>(Bs, rb, 1.f);
        {
            const float* nxt = (j0 + 128 < N_) ? lbase + (size_t)(j0 + 128) * INNER
                                               : lbase;
            ldg4(rb, nxt, INNER);
        }
        __syncthreads();
        mma_slab_p<4, 4, 4, 40, 40>(AliQ1, Bs, warp, g8, t4, acc);
        // --- row max ---
        float vm[4][2];
#pragma unroll
        for (int mt = 0; mt < 4; mt++) {
            float a0 = -1e30f, a1 = -1e30f;
#pragma unroll
            for (int nt = 0; nt < 4; nt++) {
                a0 = fmaxf(a0, fmaxf(acc[mt][nt][0], acc[mt][nt][1]));
                a1 = fmaxf(a1, fmaxf(acc[mt][nt][2], acc[mt][nt][3]));
            }
#pragma unroll
            for (int off = 1; off <= 2; off <<= 1) {
                a0 = fmaxf(a0, __shfl_xor_sync(~0u, a0, off));
                a1 = fmaxf(a1, __shfl_xor_sync(~0u, a1, off));
            }
            vm[mt][0] = a0; vm[mt][1] = a1;
        }
        if (t4 == 0)
#pragma unroll
            for (int mt = 0; mt < 4; mt++) {
                red[wn * 128 + wm * 64 + mt * 16 + g8] = vm[mt][0];
                red[wn * 128 + wm * 64 + mt * 16 + g8 + 8] = vm[mt][1];
            }
        __syncthreads();
        if (t < 128) {
            float tm = fmaxf(fmaxf(red[t], red[128 + t]),
                             fmaxf(red[256 + t], red[384 + t]));
            float mo = m_s[t];
            float mn = fmaxf(mo, tm);
            al_s[t] = __expf(mo - mn);
            m_s[t] = mn;
        }
        __syncthreads();
        // --- p = exp(mid - m_new) -> Ps (permuted), row sums ---
        float vs[4][2];
        const int swp = (g8 & 3) << 1;
        const int pbase = ((2 * t4) & 3) * 2 + ((t4 & 2) ? 1 : 0);
#pragma unroll
        for (int mt = 0; mt < 4; mt++) {
            int r = wm * 64 + mt * 16 + g8;
            float mn0 = m_s[r], mn1 = m_s[r + 8];
            float s0 = 0.f, s1 = 0.f;
#pragma unroll
            for (int nt = 0; nt < 4; nt++) {
                float p0 = __expf(acc[mt][nt][0] - mn0);
                float p1 = __expf(acc[mt][nt][1] - mn0);
                float p2 = __expf(acc[mt][nt][2] - mn1);
                float p3 = __expf(acc[mt][nt][3] - mn1);
                s0 += p0 + p1; s1 += p2 + p3;
                int gp = wn * 32 + nt * 8;
                float* rowA = Ps + r * 136 + gp;
                float* rowB = Ps + (r + 8) * 136 + gp;
                rowA[(pbase + 0) ^ swp] = cvt_tf32f(p0);
                rowA[(pbase + 2) ^ swp] = cvt_tf32f(p1);
                rowB[(pbase + 0) ^ swp] = cvt_tf32f(p2);
                rowB[(pbase + 2) ^ swp] = cvt_tf32f(p3);
            }
#pragma unroll
            for (int off = 1; off <= 2; off <<= 1) {
                s0 += __shfl_xor_sync(~0u, s0, off);
                s1 += __shfl_xor_sync(~0u, s1, off);
            }
            vs[mt][0] = s0; vs[mt][1] = s1;
        }
        if (t4 == 0)
#pragma unroll
            for (int mt = 0; mt < 4; mt++) {
                red[wn * 128 + wm * 64 + mt * 16 + g8] = vs[mt][0];
                red[wn * 128 + wm * 64 + mt * 16 + g8 + 8] = vs[mt][1];
            }
        // --- load V j-tile (k-major, stride 72) ---
        {
            int j = t >> 2, d16 = (t & 3) * 16;
#pragma unroll
            for (int p = 0; p < 2; p++) {
                int jj = j + p * 64;
                const float* src = vb + (size_t)(j0 + jj) * DH + d16;
#pragma unroll
                for (int q = 0; q < 4; q++) {
                    float4 v = *(const float4*)(src + q * 4);
                    float4 o;
                    o.x = cvt_tf32f(v.x); o.y = cvt_tf32f(v.y);
                    o.z = cvt_tf32f(v.z); o.w = cvt_tf32f(v.w);
                    *(float4*)(Vs + jj * 72 + d16 + q * 4) = o;
                }
            }
        }
        __syncthreads();
        if (t < 128)
            l_s[t] = l_s[t] * al_s[t] +
                     (red[t] + red[128 + t] + red[256 + t] + red[384 + t]);
#pragma unroll
        for (int mt = 0; mt < 2; mt++) {
            int r = wm2 * 32 + mt * 16 + g8;
            float a0 = al_s[r], a1 = al_s[r + 8];
#pragma unroll
            for (int nt = 0; nt < 4; nt++) {
                acc_o[mt][nt][0] *= a0; acc_o[mt][nt][1] *= a0;
                acc_o[mt][nt][2] *= a1; acc_o[mt][nt][3] *= a1;
            }
        }
        // --- O += P @ V ---
#pragma unroll
        for (int slab = 0; slab < 4; slab++)
            mma_pv(Ps + slab * 32, Vs + (size_t)slab * 32 * 72,
                   warp, g8, t4, acc_o);
        __syncthreads();   // Ps/Bs free for next iteration
    }
    float* yb = g_y + (size_t)b * N_ * INNER + h * 64;
#pragma unroll
    for (int mt = 0; mt < 2; mt++) {
        int r = wm2 * 32 + mt * 16 + g8;
        float inv0 = 1.0f / l_s[r], inv1 = 1.0f / l_s[r + 8];
#pragma unroll
        for (int nt = 0; nt < 4; nt++) {
            int d = wn2 * 32 + nt * 8 + 2 * t4;
            int n = i0 + r;
            *(float2*)&yb[(size_t)n * INNER + d] =
                make_float2(acc_o[mt][nt][0] * inv0, acc_o[mt][nt][1] * inv0);
            *(float2*)&yb[(size_t)(n + 8) * INNER + d] =
                make_float2(acc_o[mt][nt][2] * inv1, acc_o[mt][nt][3] * inv1);
        }
    }
}

// ---------------------------------------------------------------------------
// K4: out = y @ W2^T + bias2  (double-buffered)
// ---------------------------------------------------------------------------
__global__ __launch_bounds__(256) void k_out(float* __restrict__ out) {
    __shared__ float As[2][128 * 40], Bs[2][128 * 40];
    const int t = threadIdx.x, warp = t >> 5, lane = t & 31;
    const int g8 = lane >> 2, t4 = lane & 3;
    const int n0 = blockIdx.x * 128, m0 = blockIdx.y * 128;
    float acc[4][4][4] = {};
    R4T ra, rb;
    ldg4(ra, g_y + (size_t)m0 * INNER, INNER);
    ldg4(rb, g_w2 + (size_t)n0 * INNER, INNER);
    sts4p<40>(As[0], ra, 1.f);
    sts4p<40>(Bs[0], rb, 1.f);
    __syncthreads();
    int cur = 0;
    for (int k0 = 32; k0 < INNER; k0 += 32) {
        ldg4(ra, g_y + (size_t)m0 * INNER + k0, INNER);
        ldg4(rb, g_w2 + (size_t)n0 * INNER + k0, INNER);
        mma_slab_p<4, 4, 4, 40, 40>(As[cur], Bs[cur], warp, g8, t4, acc);
        sts4p<40>(As[cur ^ 1], ra, 1.f);
        sts4p<40>(Bs[cur ^ 1], rb, 1.f);
        __syncthreads();
        cur ^= 1;
    }
    mma_slab_p<4, 4, 4, 40, 40>(As[cur], Bs[cur], warp, g8, t4, acc);
    const int wm = warp >> 2, wn = warp & 3;
#pragma unroll
    for (int mt = 0; mt < 4; mt++)
#pragma unroll
        for (int nt = 0; nt < 4; nt++) {
            int col = n0 + wn * 32 + nt * 8 + 2 * t4;
            float b0 = g_b2[col], b1 = g_b2[col + 1];
            int r = m0 + wm * 64 + mt * 16 + g8;
            *(float2*)&out[(size_t)r * DIM + col] =
                make_float2(acc[mt][nt][0] + b0, acc[mt][nt][1] + b1);
            *(float2*)&out[(size_t)(r + 8) * DIM + col] =
                make_float2(acc[mt][nt][2] + b0, acc[mt][nt][3] + b1);
        }
}

// ---------------------------------------------------------------------------
// Precompute: W2 = Wout(.,h-block) @ Wm ; bias2 = b_out + Wout b_merge~
// ---------------------------------------------------------------------------
__global__ __launch_bounds__(256) void k_w2(const float* __restrict__ w_merge,
                                            const float* __restrict__ w_out) {
    __shared__ float wm[64 * 64];
    const int t = threadIdx.x;
    for (int i = t; i < 4096; i += 256) wm[i] = w_merge[i];
    __syncthreads();
    int idx = blockIdx.x * 256 + t;
    int c = idx >> 9, i = idx & 511;
    int h = i >> 6, d = i & 63;
    const float* wo = w_out + (size_t)c * INNER + h * 64;
    float s = 0.f;
#pragma unroll 8
    for (int dp = 0; dp < 64; dp++) s += wo[dp] * wm[dp * 64 + d];
    g_w2[idx] = s;
}

__global__ __launch_bounds__(256) void k_bias2(const float* __restrict__ w_out,
                                               const float* __restrict__ b_merge,
                                               const float* __restrict__ b_out) {
    int c = blockIdx.x * 8 + (threadIdx.x >> 5);
    int lane = threadIdx.x & 31;
    float s = 0.f;
    for (int i = lane; i < INNER; i += 32)
        s += w_out[(size_t)c * INNER + i] * b_merge[i & 63];
    for (int o = 16; o; o >>= 1) s += __shfl_xor_sync(~0u, s, o);
    if (lane == 0) g_b2[c] = b_out[c] + s;
}

__global__ __launch_bounds__(256) void k_copy(const float* __restrict__ src,
                                              float* __restrict__ dst, int n4) {
    int i = blockIdx.x * blockDim.x + threadIdx.x;
    if (i < n4) ((float4*)dst)[i] = ((const float4*)src)[i];
}

extern "C" void kernel_launch(void* const* d_in, const int* in_sizes, int n_in,
                              void* d_out, int out_size) {
    const float* x       = (const float*)d_in[0];
    const float* lidar   = (const float*)d_in[1];
    const float* w_qkv   = (const float*)d_in[2];
    const float* w_merge = (const float*)d_in[3];
    const float* b_merge = (const float*)d_in[4];
    const float* w_out   = (const float*)d_in[5];
    const float* b_out   = (const float*)d_in[6];
    const float* conv_w  = (const float*)d_in[7];
    float* out = (float*)d_out;

    const int flashSmem = (52224 + 5 * 128 + 512) * 4;   // 213.5 KB
    cudaFuncSetAttribute(k_flash, cudaFuncAttributeMaxDynamicSharedMemorySize,
                         flashSmem);

    // launch order keeps k_flash 4th (ncu captures launch #4)
    k_qkv<<<dim3(12, 64), 256>>>(x, w_qkv);
    k_lstats<<<dim3(8, G), 256>>>(lidar);
    k_w2<<<1024, 256>>>(w_merge, w_out);
    k_flash<<<dim3(8, G), 256, flashSmem>>>(lidar, conv_w);
    k_bias2<<<64, 256>>>(w_out, b_merge, b_out);
    k_out<<<dim3(4, 64), 256>>>(out);

    const int outElems = B_ * N_ * DIM;
    if (out_size >= 2 * outElems)
        k_copy<<<(outElems / 4 + 255) / 256, 256>>>(lidar, out + outElems,
                                                    outElems / 4);
}